// round 9
// baseline (speedup 1.0000x reference)
#include <cuda_runtime.h>
#include <math.h>
#include <stdint.h>

// ============================================================================
// JAX threefry2x32, 20 rounds (5 four-round groups with key injections).
// ============================================================================
struct Keys { unsigned v[12]; };

__host__ __device__ inline void threefry2x32(unsigned k0, unsigned k1,
                                             unsigned x0, unsigned x1,
                                             unsigned &o0, unsigned &o1)
{
    unsigned ks2 = k0 ^ k1 ^ 0x1BD11BDAu;
#define TF_ROT(x, r) (((x) << (r)) | ((x) >> (32 - (r))))
#define TF_RND(r) { x0 += x1; x1 = TF_ROT(x1, r); x1 ^= x0; }
    x0 += k0; x1 += k1;
    TF_RND(13) TF_RND(15) TF_RND(26) TF_RND(6)
    x0 += k1;  x1 += ks2 + 1u;
    TF_RND(17) TF_RND(29) TF_RND(16) TF_RND(24)
    x0 += ks2; x1 += k0 + 2u;
    TF_RND(13) TF_RND(15) TF_RND(26) TF_RND(6)
    x0 += k0;  x1 += k1 + 3u;
    TF_RND(17) TF_RND(29) TF_RND(16) TF_RND(24)
    x0 += k1;  x1 += ks2 + 4u;
    TF_RND(13) TF_RND(15) TF_RND(26) TF_RND(6)
    x0 += ks2; x1 += k0 + 5u;
#undef TF_RND
#undef TF_ROT
    o0 = x0; o1 = x1;
}

// Partitionable-mode random bits: counter = (0, f); draw = lane0 ^ lane1.
__device__ __forceinline__ unsigned tf_bits(unsigned k0, unsigned k1, unsigned f)
{
    unsigned o0, o1;
    threefry2x32(k0, k1, 0u, f, o0, o1);
    return o0 ^ o1;
}

// JAX gumbel — MUST stay bit-exact libdevice logf (gates integer argmax).
__device__ __forceinline__ float gumbel_f(unsigned bits)
{
    float f = __uint_as_float((bits >> 9) | 0x3f800000u) - 1.0f;
    float u = fmaxf(1.17549435e-38f, f + 1.17549435e-38f);
    return -logf(-logf(u));
}

// Order-preserving float->uint bijection (monotonic incl. +-inf).
__device__ __forceinline__ unsigned ford(float f)
{
    unsigned b = __float_as_uint(f);
    return ((int)b < 0) ? ~b : (b | 0x80000000u);
}
__device__ __forceinline__ float funord(unsigned u)
{
    unsigned b = ((int)u < 0) ? (u & 0x7fffffffu) : ~u;
    return __uint_as_float(b);
}

// ============================================================================
// Warp sample over 64 slots: lane holds t0=2*lane, t1=2*lane+1.
// Argmax exact (bit-compare, first-index ties == jnp.argmax); lp fast-math.
// ============================================================================
__device__ __forceinline__ void sample64(float s0, float s1, float g0, float g1,
                                         float mk0, float mk1, int lane,
                                         int &act, float &lp, int &cnt)
{
    float z0 = s0 + g0, z1 = s1 + g1;
    bool hi = (z1 > z0);                       // strict: first-index ties
    float zv = hi ? z1 : z0;
    int   zi = 2 * lane + (hi ? 1 : 0);
    float m  = fmaxf(s0, s1);

    unsigned zk = ford(zv);
    unsigned zmax = __reduce_max_sync(0xffffffffu, zk);
    act = __reduce_min_sync(0xffffffffu, (zk == zmax) ? zi : 0x7fffffff);

    float mmax = funord(__reduce_max_sync(0xffffffffu, ford(m)));

    float e = __expf(s0 - mmax) + __expf(s1 - mmax);
    int ei = (int)(e * 16777216.0f);           // 2^24 scale; sum < 2^31
    int esum = __reduce_add_sync(0xffffffffu, ei);
    float ef = (float)esum * 5.9604644775390625e-08f;  // / 2^24

    float ssel = (act & 1) ? s1 : s0;
    float zs = __shfl_sync(0xffffffffu, ssel, act >> 1);

    cnt = ((mk0 == 0.0f) ? 1 : 0) + ((mk1 == 0.0f) ? 1 : 0);

    lp = zs - mmax - __logf(ef);
}

// ============================================================================
// Main kernel: one warp per batch row b. All RNG + loads hoisted upfront
// for maximum ILP; only REDUX chains and the rbs recurrence stay serial.
// ============================================================================
__global__ void __launch_bounds__(256) pt_kernel(
    const float* __restrict__ order_mask,   // (B,7)
    const int*   __restrict__ budgets,      // (B,7,4)
    const float* __restrict__ tile_masks,   // (B,7,4,64)
    const int*   __restrict__ loop_ind_p,   // scalar
    const float* __restrict__ rbs_in,       // (B,)
    const int*   __restrict__ t2max_in,     // (B,)
    const float* __restrict__ mtemp_in,     // (B,)
    const int*   __restrict__ spmax_in,     // (B,)
    const int*   __restrict__ spmin_in,     // (B,)
    const float* __restrict__ order_logit,  // (B,7)
    const float* __restrict__ tile_logits,  // (B,4,64)
    const float* __restrict__ sp_logit,     // (B,64)
    float* __restrict__ out,
    int B, Keys keys)
{
    const int lane = threadIdx.x & 31;
    const int b = (int)((blockIdx.x * blockDim.x + threadIdx.x) >> 5);
    if (b >= B) return;

    const int li = loop_ind_p[0];

    const int t0 = 2 * lane, t1 = t0 + 1;
    const unsigned f0 = (unsigned)(b * 64 + t0);
    const unsigned f1 = f0 + 1u;

    // ---- hoisted scalar + vector loads (latency overlapped w/ threefry) ----
    const int   smx   = spmax_in[b];
    const int   smn   = spmin_in[b];
    const int   t2mxi = t2max_in[b];
    const float mtemp = mtemp_in[b];
    float rbs         = rbs_in[b];
    int   bud[3];
#pragma unroll
    for (int p = 1; p < 4; p++) bud[p - 1] = budgets[(b * 7 + li) * 4 + p];

    const int mrow = ((b * 7 + li) * 4) * 64;      // tile_masks row base
    float2 base   = *reinterpret_cast<const float2*>(tile_masks + mrow + t0);
    float2 sp_lg  = *reinterpret_cast<const float2*>(sp_logit + b * 64 + t0);
    float2 lg0    = *reinterpret_cast<const float2*>(tile_logits + (b * 4) * 64 + t0);
    float2 tmv[3], lgv[3];
#pragma unroll
    for (int p = 1; p < 4; p++) {
        tmv[p - 1] = *reinterpret_cast<const float2*>(tile_masks + mrow + p * 64 + t0);
        lgv[p - 1] = *reinterpret_cast<const float2*>(tile_logits + (b * 4 + p) * 64 + t0);
    }
    float omask_v = 0.0f, ologit_v = 0.0f;
    if (lane < 7) {
        omask_v  = order_mask[b * 7 + lane];
        ologit_v = order_logit[b * 7 + lane];
    }

    // ---- hoisted threefry: all 11 evals (pure int, max ILP) ----
    unsigned bo  = tf_bits(keys.v[0],  keys.v[1],  (unsigned)(b * 7 + (lane < 7 ? lane : 0)));
    unsigned bs0 = tf_bits(keys.v[2],  keys.v[3],  f0);
    unsigned bs1 = tf_bits(keys.v[2],  keys.v[3],  f1);
    unsigned bt0[4], bt1[4];
#pragma unroll
    for (int p = 0; p < 4; p++) {
        bt0[p] = tf_bits(keys.v[4 + 2 * p], keys.v[5 + 2 * p], f0);
        bt1[p] = tf_bits(keys.v[4 + 2 * p], keys.v[5 + 2 * p], f1);
    }

    // ---- hoisted gumbels: 11 independent -log(-log(u)) chains interleave ----
    float g_o  = gumbel_f(bo);
    float gs0  = gumbel_f(bs0), gs1 = gumbel_f(bs1);
    float gt0[4], gt1[4];
#pragma unroll
    for (int p = 0; p < 4; p++) {
        gt0[p] = gumbel_f(bt0[p]);
        gt1[p] = gumbel_f(bt1[p]);
    }

    float lp[6];
    int cnt[6];
    int tacts[4];
    int oact, spact;

    // ---------------- order sampling (T=7, keys[0]) ----------------
    {
        float s = (lane < 7) ? (ologit_v + omask_v) : -INFINITY;
        float zv = s + g_o;                    // lanes >= 7: -inf, never wins
        unsigned zk = ford(zv);
        unsigned zmax = __reduce_max_sync(0xffffffffu, zk);
        oact = __reduce_min_sync(0xffffffffu, (zk == zmax) ? lane : 0x7fffffff);
        float mmax = funord(__reduce_max_sync(0xffffffffu, ford(s)));
        float e = __expf(s - mmax);
        int ei = (int)(e * 16777216.0f);
        int esum = __reduce_add_sync(0xffffffffu, ei);
        float ef = (float)esum * 5.9604644775390625e-08f;
        float zs = __shfl_sync(0xffffffffu, s, oact);
        cnt[0] = (lane < 7 && omask_v == 0.0f) ? 1 : 0;
        lp[0] = zs - mmax - __logf(ef);
    }

    // ---------------- sp_tile2 sampling (T=64, keys[1]) ----------------
    {
        float mk0 = (t0 > smx || t0 < smn) ? -INFINITY : base.x;
        float mk1 = (t1 > smx || t1 < smn) ? -INFINITY : base.y;
        sample64(sp_lg.x + mk0, sp_lg.y + mk1, gs0, gs1, mk0, mk1, lane,
                 spact, lp[5], cnt[5]);
    }

    // ---------------- tile2 sampling (p=0, keys[2]) ----------------
    {
        int t2min = spact;
        int t2mx = min(t2mxi, t2min + (int)mtemp);
        float mk0 = (t0 > t2mx || t0 < t2min) ? -INFINITY : base.x;
        float mk1 = (t1 > t2mx || t1 < t2min) ? -INFINITY : base.y;
        sample64(lg0.x + mk0, lg0.y + mk1, gt0[0], gt1[0], mk0, mk1, lane,
                 tacts[0], lp[1], cnt[1]);
    }

    // ---------------- p = 1..3 chain (keys[3..5]) ----------------
    int ta = tacts[0];
    const float primef[3] = { 2.0f, 3.0f, 5.0f };
    const float denom[3]  = { 1.5849625f,    // (float)np.log2(3)
                              2.321928f,     // (float)np.log2(5)
                              2.8073549f };  // (float)np.log2(7)
#pragma unroll
    for (int p = 1; p < 4; p++) {
        // rbs chain — byte-identical to the passing R2..R7 version:
        rbs = rbs / powf(primef[p - 1], (float)ta);
        float tmf = logf(fmaxf(rbs, 1.0f)) / 0.69314718f;  // jnp.log2
        tmf = tmf / denom[p - 1];                          // / np.log2(prime)
        int tmax = (int)tmf;             // f32->s32 truncation toward zero
        tmax = max(0, min(tmax, 63));    // clip(0, T-1)
        tmax = min(tmax, bud[p - 1]);
        float mk0 = (t0 > tmax) ? -INFINITY : tmv[p - 1].x;
        float mk1 = (t1 > tmax) ? -INFINITY : tmv[p - 1].y;
        int a;
        sample64(lgv[p - 1].x + mk0, lgv[p - 1].y + mk1,
                 gt0[p], gt1[p], mk0, mk1, lane,
                 a, lp[p + 1], cnt[p + 1]);
        tacts[p] = a;
        ta = a;
    }

    // ---- deferred lpm: 6 counts in 2 packed REDUX (fields sum <= 64 < 256) ----
    unsigned packA = (unsigned)cnt[0] | ((unsigned)cnt[1] << 8)
                   | ((unsigned)cnt[2] << 16) | ((unsigned)cnt[3] << 24);
    unsigned packB = (unsigned)cnt[4] | ((unsigned)cnt[5] << 8);
    packA = __reduce_add_sync(0xffffffffu, packA);
    packB = __reduce_add_sync(0xffffffffu, packB);

    // ---------------- write outputs ----------------
    // layout: order_action(B) | tile_actions(B,4) | sp_tile_actions(B,4)
    //         | log_probs(B,6) | log_prob_masks(B,6)   — all as f32
    if (lane == 0) {
        float lpmv[6];
        lpmv[0] = (((packA)       & 0xffu) > 1) ? 1.0f : 0.0f;
        lpmv[1] = (((packA >>  8) & 0xffu) > 1) ? 1.0f : 0.0f;
        lpmv[2] = (((packA >> 16) & 0xffu) > 1) ? 1.0f : 0.0f;
        lpmv[3] = (((packA >> 24) & 0xffu) > 1) ? 1.0f : 0.0f;
        lpmv[4] = (((packB)       & 0xffu) > 1) ? 1.0f : 0.0f;
        lpmv[5] = (((packB >>  8) & 0xffu) > 1) ? 1.0f : 0.0f;

        out[b] = (float)oact;
        float* ta_out = out + B;
        ta_out[b * 4 + 0] = (float)tacts[0];
        ta_out[b * 4 + 1] = (float)tacts[1];
        ta_out[b * 4 + 2] = (float)tacts[2];
        ta_out[b * 4 + 3] = (float)tacts[3];
        float* sp_out = out + 5 * B;
        sp_out[b * 4 + 0] = (float)spact;
        sp_out[b * 4 + 1] = 0.0f;
        sp_out[b * 4 + 2] = 0.0f;
        sp_out[b * 4 + 3] = 0.0f;
        float* lp_out = out + 9 * B;
        float* lm_out = out + 15 * B;
#pragma unroll
        for (int k = 0; k < 6; k++) {
            lp_out[b * 6 + k] = lp[k];
            lm_out[b * 6 + k] = lpmv[k];
        }
    }
}

// ============================================================================
// Launch: keys = jax.random.split(jax.random.key(1), 6), partitionable mode.
// ============================================================================
extern "C" void kernel_launch(void* const* d_in, const int* in_sizes, int n_in,
                              void* d_out, int out_size)
{
    int B = in_sizes[6];  // remain_buffer_size is (B,)

    Keys keys;
    for (int i = 0; i < 6; i++) {
        unsigned o0, o1;
        threefry2x32(0u, 1u, 0u, (unsigned)i, o0, o1);
        keys.v[2 * i]     = o0;
        keys.v[2 * i + 1] = o1;
    }

    int threads = 256;
    int blocks = (B * 32 + threads - 1) / threads;

    pt_kernel<<<blocks, threads>>>(
        (const float*)d_in[1],   // order_mask
        (const int*)  d_in[2],   // tile_remain_budgets
        (const float*)d_in[3],   // tile_masks
        (const int*)  d_in[5],   // loop_ind
        (const float*)d_in[6],   // remain_buffer_size
        (const int*)  d_in[7],   // tile2_max
        (const float*)d_in[8],   // max_temporal_tile2
        (const int*)  d_in[9],   // sp_tile2_max
        (const int*)  d_in[10],  // sp_tile2_min
        (const float*)d_in[11],  // order_logit
        (const float*)d_in[12],  // tile_logits
        (const float*)d_in[13],  // sp_tile2_logit
        (float*)d_out, B, keys);
}

// round 10
// speedup vs baseline: 1.2209x; 1.2209x over previous
#include <cuda_runtime.h>
#include <math.h>
#include <stdint.h>

// ============================================================================
// JAX threefry2x32, 20 rounds (5 four-round groups with key injections).
// ============================================================================
struct Keys { unsigned v[12]; };

__host__ __device__ inline void threefry2x32(unsigned k0, unsigned k1,
                                             unsigned x0, unsigned x1,
                                             unsigned &o0, unsigned &o1)
{
    unsigned ks2 = k0 ^ k1 ^ 0x1BD11BDAu;
#define TF_ROT(x, r) (((x) << (r)) | ((x) >> (32 - (r))))
#define TF_RND(r) { x0 += x1; x1 = TF_ROT(x1, r); x1 ^= x0; }
    x0 += k0; x1 += k1;
    TF_RND(13) TF_RND(15) TF_RND(26) TF_RND(6)
    x0 += k1;  x1 += ks2 + 1u;
    TF_RND(17) TF_RND(29) TF_RND(16) TF_RND(24)
    x0 += ks2; x1 += k0 + 2u;
    TF_RND(13) TF_RND(15) TF_RND(26) TF_RND(6)
    x0 += k0;  x1 += k1 + 3u;
    TF_RND(17) TF_RND(29) TF_RND(16) TF_RND(24)
    x0 += k1;  x1 += ks2 + 4u;
    TF_RND(13) TF_RND(15) TF_RND(26) TF_RND(6)
    x0 += ks2; x1 += k0 + 5u;
#undef TF_RND
#undef TF_ROT
    o0 = x0; o1 = x1;
}

// Partitionable-mode random bits: counter = (0, f); draw = lane0 ^ lane1.
__device__ __forceinline__ unsigned tf_bits(unsigned k0, unsigned k1, unsigned f)
{
    unsigned o0, o1;
    threefry2x32(k0, k1, 0u, f, o0, o1);
    return o0 ^ o1;
}

// JAX gumbel — MUST stay bit-exact libdevice logf (gates integer argmax).
__device__ __forceinline__ float gumbel_f(unsigned bits)
{
    float f = __uint_as_float((bits >> 9) | 0x3f800000u) - 1.0f;
    float u = fmaxf(1.17549435e-38f, f + 1.17549435e-38f);
    return -logf(-logf(u));
}

// Order-preserving float->uint bijection (monotonic incl. +-inf).
__device__ __forceinline__ unsigned ford(float f)
{
    unsigned b = __float_as_uint(f);
    return ((int)b < 0) ? ~b : (b | 0x80000000u);
}
__device__ __forceinline__ float funord(unsigned u)
{
    unsigned b = ((int)u < 0) ? (u & 0x7fffffffu) : ~u;
    return __uint_as_float(b);
}

// ============================================================================
// Warp sample over 64 slots: lane holds t0=2*lane, t1=2*lane+1.
// Argmax exact (bit-compare, first-index ties == jnp.argmax); lp fast-math.
// ============================================================================
__device__ __forceinline__ void sample64(float s0, float s1, float g0, float g1,
                                         float mk0, float mk1, int lane,
                                         int &act, float &lp, int &cnt)
{
    float z0 = s0 + g0, z1 = s1 + g1;
    bool hi = (z1 > z0);                       // strict: first-index ties
    float zv = hi ? z1 : z0;
    int   zi = 2 * lane + (hi ? 1 : 0);
    float m  = fmaxf(s0, s1);

    unsigned zk = ford(zv);
    unsigned zmax = __reduce_max_sync(0xffffffffu, zk);
    act = __reduce_min_sync(0xffffffffu, (zk == zmax) ? zi : 0x7fffffff);

    float mmax = funord(__reduce_max_sync(0xffffffffu, ford(m)));

    float e = __expf(s0 - mmax) + __expf(s1 - mmax);
    int ei = (int)(e * 16777216.0f);           // 2^24 scale; sum < 2^31
    int esum = __reduce_add_sync(0xffffffffu, ei);
    float ef = (float)esum * 5.9604644775390625e-08f;  // / 2^24

    float ssel = (act & 1) ? s1 : s0;
    float zs = __shfl_sync(0xffffffffu, ssel, act >> 1);

    cnt = ((mk0 == 0.0f) ? 1 : 0) + ((mk1 == 0.0f) ? 1 : 0);

    lp = zs - mmax - __logf(ef);
}

// ============================================================================
// Main kernel: one warp per batch row b. All RNG + loads hoisted upfront
// for maximum ILP; only REDUX chains and the rbs recurrence stay serial.
// ============================================================================
__global__ void __launch_bounds__(256) pt_kernel(
    const float* __restrict__ order_mask,   // (B,7)
    const int*   __restrict__ budgets,      // (B,7,4)
    const float* __restrict__ tile_masks,   // (B,7,4,64)
    const int*   __restrict__ loop_ind_p,   // scalar
    const float* __restrict__ rbs_in,       // (B,)
    const int*   __restrict__ t2max_in,     // (B,)
    const float* __restrict__ mtemp_in,     // (B,)
    const int*   __restrict__ spmax_in,     // (B,)
    const int*   __restrict__ spmin_in,     // (B,)
    const float* __restrict__ order_logit,  // (B,7)
    const float* __restrict__ tile_logits,  // (B,4,64)
    const float* __restrict__ sp_logit,     // (B,64)
    float* __restrict__ out,
    int B, Keys keys)
{
    const int lane = threadIdx.x & 31;
    const int b = (int)((blockIdx.x * blockDim.x + threadIdx.x) >> 5);
    if (b >= B) return;

    const int li = loop_ind_p[0];

    const int t0 = 2 * lane, t1 = t0 + 1;
    const unsigned f0 = (unsigned)(b * 64 + t0);
    const unsigned f1 = f0 + 1u;

    // ---- hoisted scalar + vector loads (latency overlapped w/ threefry) ----
    const int   smx   = spmax_in[b];
    const int   smn   = spmin_in[b];
    const int   t2mxi = t2max_in[b];
    const float mtemp = mtemp_in[b];
    float rbs         = rbs_in[b];
    int   bud[3];
#pragma unroll
    for (int p = 1; p < 4; p++) bud[p - 1] = budgets[(b * 7 + li) * 4 + p];

    const int mrow = ((b * 7 + li) * 4) * 64;      // tile_masks row base
    float2 base   = *reinterpret_cast<const float2*>(tile_masks + mrow + t0);
    float2 sp_lg  = *reinterpret_cast<const float2*>(sp_logit + b * 64 + t0);
    float2 lg0    = *reinterpret_cast<const float2*>(tile_logits + (b * 4) * 64 + t0);
    float2 tmv[3], lgv[3];
#pragma unroll
    for (int p = 1; p < 4; p++) {
        tmv[p - 1] = *reinterpret_cast<const float2*>(tile_masks + mrow + p * 64 + t0);
        lgv[p - 1] = *reinterpret_cast<const float2*>(tile_logits + (b * 4 + p) * 64 + t0);
    }
    float omask_v = 0.0f, ologit_v = 0.0f;
    if (lane < 7) {
        omask_v  = order_mask[b * 7 + lane];
        ologit_v = order_logit[b * 7 + lane];
    }

    // ---- hoisted threefry: all 11 evals (pure int, max ILP) ----
    unsigned bo  = tf_bits(keys.v[0],  keys.v[1],  (unsigned)(b * 7 + (lane < 7 ? lane : 0)));
    unsigned bs0 = tf_bits(keys.v[2],  keys.v[3],  f0);
    unsigned bs1 = tf_bits(keys.v[2],  keys.v[3],  f1);
    unsigned bt0[4], bt1[4];
#pragma unroll
    for (int p = 0; p < 4; p++) {
        bt0[p] = tf_bits(keys.v[4 + 2 * p], keys.v[5 + 2 * p], f0);
        bt1[p] = tf_bits(keys.v[4 + 2 * p], keys.v[5 + 2 * p], f1);
    }

    // ---- hoisted gumbels: 11 independent -log(-log(u)) chains interleave ----
    float g_o  = gumbel_f(bo);
    float gs0  = gumbel_f(bs0), gs1 = gumbel_f(bs1);
    float gt0[4], gt1[4];
#pragma unroll
    for (int p = 0; p < 4; p++) {
        gt0[p] = gumbel_f(bt0[p]);
        gt1[p] = gumbel_f(bt1[p]);
    }

    float lp[6];
    int cnt[6];
    int tacts[4];
    int oact, spact;

    // ---------------- order sampling (T=7, keys[0]) ----------------
    {
        float s = (lane < 7) ? (ologit_v + omask_v) : -INFINITY;
        float zv = s + g_o;                    // lanes >= 7: -inf, never wins
        unsigned zk = ford(zv);
        unsigned zmax = __reduce_max_sync(0xffffffffu, zk);
        oact = __reduce_min_sync(0xffffffffu, (zk == zmax) ? lane : 0x7fffffff);
        float mmax = funord(__reduce_max_sync(0xffffffffu, ford(s)));
        float e = __expf(s - mmax);
        int ei = (int)(e * 16777216.0f);
        int esum = __reduce_add_sync(0xffffffffu, ei);
        float ef = (float)esum * 5.9604644775390625e-08f;
        float zs = __shfl_sync(0xffffffffu, s, oact);
        cnt[0] = (lane < 7 && omask_v == 0.0f) ? 1 : 0;
        lp[0] = zs - mmax - __logf(ef);
    }

    // ---------------- sp_tile2 sampling (T=64, keys[1]) ----------------
    {
        float mk0 = (t0 > smx || t0 < smn) ? -INFINITY : base.x;
        float mk1 = (t1 > smx || t1 < smn) ? -INFINITY : base.y;
        sample64(sp_lg.x + mk0, sp_lg.y + mk1, gs0, gs1, mk0, mk1, lane,
                 spact, lp[5], cnt[5]);
    }

    // ---------------- tile2 sampling (p=0, keys[2]) ----------------
    {
        int t2min = spact;
        int t2mx = min(t2mxi, t2min + (int)mtemp);
        float mk0 = (t0 > t2mx || t0 < t2min) ? -INFINITY : base.x;
        float mk1 = (t1 > t2mx || t1 < t2min) ? -INFINITY : base.y;
        sample64(lg0.x + mk0, lg0.y + mk1, gt0[0], gt1[0], mk0, mk1, lane,
                 tacts[0], lp[1], cnt[1]);
    }

    // ---------------- p = 1..3 chain (keys[3..5]) ----------------
    int ta = tacts[0];
    const float primef[3] = { 2.0f, 3.0f, 5.0f };
    const float denom[3]  = { 1.5849625f,    // (float)np.log2(3)
                              2.321928f,     // (float)np.log2(5)
                              2.8073549f };  // (float)np.log2(7)
#pragma unroll
    for (int p = 1; p < 4; p++) {
        // rbs chain — byte-identical to the passing R2..R9 version:
        rbs = rbs / powf(primef[p - 1], (float)ta);
        float tmf = logf(fmaxf(rbs, 1.0f)) / 0.69314718f;  // jnp.log2
        tmf = tmf / denom[p - 1];                          // / np.log2(prime)
        int tmax = (int)tmf;             // f32->s32 truncation toward zero
        tmax = max(0, min(tmax, 63));    // clip(0, T-1)
        tmax = min(tmax, bud[p - 1]);
        float mk0 = (t0 > tmax) ? -INFINITY : tmv[p - 1].x;
        float mk1 = (t1 > tmax) ? -INFINITY : tmv[p - 1].y;
        int a;
        sample64(lgv[p - 1].x + mk0, lgv[p - 1].y + mk1,
                 gt0[p], gt1[p], mk0, mk1, lane,
                 a, lp[p + 1], cnt[p + 1]);
        tacts[p] = a;
        ta = a;
    }

    // ---- deferred lpm: 6 counts in 2 packed REDUX (fields sum <= 64 < 256) ----
    unsigned packA = (unsigned)cnt[0] | ((unsigned)cnt[1] << 8)
                   | ((unsigned)cnt[2] << 16) | ((unsigned)cnt[3] << 24);
    unsigned packB = (unsigned)cnt[4] | ((unsigned)cnt[5] << 8);
    packA = __reduce_add_sync(0xffffffffu, packA);
    packB = __reduce_add_sync(0xffffffffu, packB);

    // ---------------- write outputs (vectorized, lane 0) ----------------
    // layout: order_action(B) | tile_actions(B,4) | sp_tile_actions(B,4)
    //         | log_probs(B,6) | log_prob_masks(B,6)   — all as f32
    if (lane == 0) {
        float lpmv[6];
        lpmv[0] = (((packA)       & 0xffu) > 1) ? 1.0f : 0.0f;
        lpmv[1] = (((packA >>  8) & 0xffu) > 1) ? 1.0f : 0.0f;
        lpmv[2] = (((packA >> 16) & 0xffu) > 1) ? 1.0f : 0.0f;
        lpmv[3] = (((packA >> 24) & 0xffu) > 1) ? 1.0f : 0.0f;
        lpmv[4] = (((packB)       & 0xffu) > 1) ? 1.0f : 0.0f;
        lpmv[5] = (((packB >>  8) & 0xffu) > 1) ? 1.0f : 0.0f;

        out[b] = (float)oact;
        // tile_actions: 16B-aligned (out+B is 16B-aligned, stride 16B)
        *reinterpret_cast<float4*>(out + B + b * 4) =
            make_float4((float)tacts[0], (float)tacts[1],
                        (float)tacts[2], (float)tacts[3]);
        // sp_tile_actions: 16B-aligned
        *reinterpret_cast<float4*>(out + 5 * B + b * 4) =
            make_float4((float)spact, 0.0f, 0.0f, 0.0f);
        // log_probs / log_prob_masks: stride 24B -> 3x float2 (8B-aligned)
        float* lp_out = out + 9 * B + b * 6;
        *reinterpret_cast<float2*>(lp_out + 0) = make_float2(lp[0], lp[1]);
        *reinterpret_cast<float2*>(lp_out + 2) = make_float2(lp[2], lp[3]);
        *reinterpret_cast<float2*>(lp_out + 4) = make_float2(lp[4], lp[5]);
        float* lm_out = out + 15 * B + b * 6;
        *reinterpret_cast<float2*>(lm_out + 0) = make_float2(lpmv[0], lpmv[1]);
        *reinterpret_cast<float2*>(lm_out + 2) = make_float2(lpmv[2], lpmv[3]);
        *reinterpret_cast<float2*>(lm_out + 4) = make_float2(lpmv[4], lpmv[5]);
    }
}

// ============================================================================
// Launch: keys = jax.random.split(jax.random.key(1), 6), partitionable mode.
// ============================================================================
extern "C" void kernel_launch(void* const* d_in, const int* in_sizes, int n_in,
                              void* d_out, int out_size)
{
    int B = in_sizes[6];  // remain_buffer_size is (B,)

    Keys keys;
    for (int i = 0; i < 6; i++) {
        unsigned o0, o1;
        threefry2x32(0u, 1u, 0u, (unsigned)i, o0, o1);
        keys.v[2 * i]     = o0;
        keys.v[2 * i + 1] = o1;
    }

    int threads = 256;
    int blocks = (B * 32 + threads - 1) / threads;

    pt_kernel<<<blocks, threads>>>(
        (const float*)d_in[1],   // order_mask
        (const int*)  d_in[2],   // tile_remain_budgets
        (const float*)d_in[3],   // tile_masks
        (const int*)  d_in[5],   // loop_ind
        (const float*)d_in[6],   // remain_buffer_size
        (const int*)  d_in[7],   // tile2_max
        (const float*)d_in[8],   // max_temporal_tile2
        (const int*)  d_in[9],   // sp_tile2_max
        (const int*)  d_in[10],  // sp_tile2_min
        (const float*)d_in[11],  // order_logit
        (const float*)d_in[12],  // tile_logits
        (const float*)d_in[13],  // sp_tile2_logit
        (float*)d_out, B, keys);
}